// round 3
// baseline (speedup 1.0000x reference)
#include <cuda_runtime.h>
#include <cuda_bf16.h>

// Problem constants
#define B_    32
#define CIN   256
#define HIN   64
#define WIN   64
#define COUT  32
#define KH    9
#define KW    9
#define OH    28
#define OW    28
#define T_    8
#define NPOS  (COUT*OH*OW)   // 25088

// Row tile: 7 output rows per block -> 4 tiles cover 28 rows.
#define TH    7
#define XROWS (2*(TH-1)+KH)  // 21 input rows needed
#define NTHREADS 224         // 7 warps: 28 spatial groups x 8 oc groups

// Transposed weights: [ic][k][oc], k = kh*9+kw  (2.65 MB device scratch)
__device__ float g_wt[CIN * KH * KW * COUT];

__global__ void transpose_w_kernel(const float* __restrict__ W) {
    int i = blockIdx.x * blockDim.x + threadIdx.x;
    const int total = CIN * KH * KW * COUT;
    if (i >= total) return;
    int ic = i / (KH * KW * COUT);
    int r  = i % (KH * KW * COUT);
    int k  = r / COUT;
    int oc = r % COUT;
    // W layout: [oc][ic][kh][kw]
    g_wt[i] = W[((size_t)oc * CIN + ic) * (KH * KW) + k];
}

__global__ __launch_bounds__(NTHREADS, 1)
void primary_layer_kernel(const float* __restrict__ x,
                          const float* __restrict__ bias,
                          float* __restrict__ out) {
    __shared__ float sx[XROWS * WIN];        // 21*64 = 1344 floats
    __shared__ float sw[KH * KW * COUT];     // 81*32 = 2592 floats

    const int b   = blockIdx.y;
    const int rt  = blockIdx.x;              // row tile 0..3
    const int oh0 = rt * TH;
    const int ih0 = oh0 * 2;

    const int tid = threadIdx.x;
    const int ocg = tid & 7;                 // 8 oc groups of 4
    const int sg  = tid >> 3;                // 28 spatial groups
    const int row = sg >> 2;                 // 0..6
    const int cg  = sg & 3;                  // col group: ow base = cg*7

    float acc[TH][4];
    #pragma unroll
    for (int j = 0; j < TH; ++j)
        #pragma unroll
        for (int o = 0; o < 4; ++o) acc[j][o] = 0.f;

    const float4* __restrict__ xg4_base =
        reinterpret_cast<const float4*>(x + ((size_t)b * CIN) * (HIN * WIN) + ih0 * WIN);
    const float4* __restrict__ wt4_base = reinterpret_cast<const float4*>(g_wt);

    for (int ic = 0; ic < CIN; ++ic) {
        // ---- load x tile (21 full 64-wide rows, contiguous) as float4 ----
        const float4* xg4 = xg4_base + (size_t)ic * (HIN * WIN / 4);
        float4* sx4 = reinterpret_cast<float4*>(sx);
        #pragma unroll 2
        for (int i = tid; i < XROWS * WIN / 4; i += NTHREADS) sx4[i] = xg4[i];

        // ---- load transposed weights for this ic (contiguous) as float4 ----
        const float4* wg4 = wt4_base + (size_t)ic * (KH * KW * COUT / 4);
        float4* sw4 = reinterpret_cast<float4*>(sw);
        #pragma unroll 3
        for (int i = tid; i < KH * KW * COUT / 4; i += NTHREADS) sw4[i] = wg4[i];

        __syncthreads();

        // ---- compute ----
        #pragma unroll 1
        for (int kh = 0; kh < KH; ++kh) {
            const float* xr = &sx[(2 * row + kh) * WIN + cg * 14];
            const float* wr = &sw[(kh * KW) * COUT + ocg * 4];
            #pragma unroll
            for (int kw = 0; kw < KW; ++kw) {
                float4 wv = *reinterpret_cast<const float4*>(wr + kw * COUT);
                float xv[TH];
                #pragma unroll
                for (int j = 0; j < TH; ++j) xv[j] = xr[kw + 2 * j];
                #pragma unroll
                for (int j = 0; j < TH; ++j) {
                    acc[j][0] = fmaf(xv[j], wv.x, acc[j][0]);
                    acc[j][1] = fmaf(xv[j], wv.y, acc[j][1]);
                    acc[j][2] = fmaf(xv[j], wv.z, acc[j][2]);
                    acc[j][3] = fmaf(xv[j], wv.w, acc[j][3]);
                }
            }
        }
        __syncthreads();
    }

    // ---- epilogue: bias + squash, write 8 identical T copies ----
    float4* out4 = reinterpret_cast<float4*>(out);
    #pragma unroll
    for (int o = 0; o < 4; ++o) {
        const int oc = ocg * 4 + o;
        const float bv = bias[oc];
        #pragma unroll
        for (int j = 0; j < TH; ++j) {
            float v = acc[j][o] + bv;
            float sq = 8.f * v * v;
            float scale = (sq / (1.f + sq)) * rsqrtf(sq + 1e-8f);
            float sv = v * scale;
            const int oh = oh0 + row;
            const int ow = cg * TH + j;
            const int n  = oc * (OH * OW) + oh * OW + ow;
            const size_t base = ((size_t)b * NPOS + n) * 2;  // in float4 units (8 floats)
            float4 f4 = make_float4(sv, sv, sv, sv);
            out4[base]     = f4;
            out4[base + 1] = f4;
        }
    }
}

extern "C" void kernel_launch(void* const* d_in, const int* in_sizes, int n_in,
                              void* d_out, int out_size) {
    const float* x    = (const float*)d_in[0];
    const float* W    = (const float*)d_in[1];
    const float* bias = (const float*)d_in[2];
    float* out = (float*)d_out;

    // 1) transpose weights into [ic][k][oc]
    const int wtotal = CIN * KH * KW * COUT;
    transpose_w_kernel<<<(wtotal + 255) / 256, 256>>>(W);

    // 2) fused conv + bias + squash + broadcast write
    dim3 grid(OH / TH, B_);   // (4, 32) = 128 blocks
    primary_layer_kernel<<<grid, NTHREADS>>>(x, bias, out);
}

// round 4
// speedup vs baseline: 1.7326x; 1.7326x over previous
#include <cuda_runtime.h>
#include <cuda_bf16.h>
#include <cstdint>

// Problem constants
#define B_    32
#define CIN   256
#define HIN   64
#define WIN   64
#define COUT  32
#define KH    9
#define KW    9
#define OH    28
#define OW    28
#define T_    8
#define NPOS  (COUT*OH*OW)   // 25088

// Conv-kernel tiling: 4 output rows per block, ic split into 2 halves.
#define THA    4
#define XROWSA (2*(THA-1)+KH)   // 15 input rows
#define NICH   (CIN/2)          // 128 ic per half
#define NTHR_A 128              // 16 spatial groups x 8 oc groups

// Transposed weights: [ic][k][oc], k = kh*9+kw  (2.65 MB)
__device__ float g_wt[CIN * KH * KW * COUT];
// Partial conv sums: [half][b][oc][oh][ow]  (51.4 MB)
__device__ float g_scratch[2 * B_ * COUT * OH * OW];

__device__ __forceinline__ void cp_async16(void* smem, const void* gmem) {
    uint32_t s = (uint32_t)__cvta_generic_to_shared(smem);
    asm volatile("cp.async.cg.shared.global [%0], [%1], 16;\n" :: "r"(s), "l"(gmem));
}
__device__ __forceinline__ void cp_commit() {
    asm volatile("cp.async.commit_group;\n" ::);
}
__device__ __forceinline__ void cp_wait_all() {
    asm volatile("cp.async.wait_group 0;\n" ::);
}

__global__ void transpose_w_kernel(const float* __restrict__ W) {
    int i = blockIdx.x * blockDim.x + threadIdx.x;
    const int total = CIN * KH * KW * COUT;
    if (i >= total) return;
    int ic = i / (KH * KW * COUT);
    int r  = i % (KH * KW * COUT);
    int k  = r / COUT;
    int oc = r % COUT;
    g_wt[i] = W[((size_t)oc * CIN + ic) * (KH * KW) + k];
}

__global__ __launch_bounds__(NTHR_A)
void conv_partial_kernel(const float* __restrict__ x) {
    __shared__ float sx[2][XROWSA * WIN];    // 2 * 960 floats
    __shared__ float sw[2][KH * KW * COUT];  // 2 * 2592 floats

    const int rt   = blockIdx.x;     // 0..6 row tile
    const int half = blockIdx.y;     // 0..1 ic half
    const int b    = blockIdx.z;     // 0..31 batch
    const int oh0  = rt * THA;
    const int ih0  = oh0 * 2;

    const int tid = threadIdx.x;
    const int ocg = tid & 7;          // 8 oc groups of 4
    const int sg  = tid >> 3;         // 16 spatial groups
    const int row = sg >> 2;          // 0..3 output row within tile
    const int cg  = sg & 3;           // col group: ow base = cg*7

    const float* __restrict__ xg =
        x + ((size_t)b * CIN + half * NICH) * (HIN * WIN) + (size_t)ih0 * WIN;
    const float* __restrict__ wg = g_wt + (size_t)(half * NICH) * (KH * KW * COUT);

    float acc[7][4];
    #pragma unroll
    for (int j = 0; j < 7; ++j)
        #pragma unroll
        for (int o = 0; o < 4; ++o) acc[j][o] = 0.f;

    // stage loader: ic tile -> smem buffer via cp.async
    auto load_stage = [&](int buf, int ic) {
        const float4* xs = reinterpret_cast<const float4*>(xg + (size_t)ic * (HIN * WIN));
        float4* dx = reinterpret_cast<float4*>(sx[buf]);
        #pragma unroll
        for (int i = tid; i < XROWSA * WIN / 4; i += NTHR_A)   // 240 -> <=2 per thread
            cp_async16(dx + i, xs + i);
        const float4* ws = reinterpret_cast<const float4*>(wg + (size_t)ic * (KH * KW * COUT));
        float4* dw = reinterpret_cast<float4*>(sw[buf]);
        #pragma unroll
        for (int i = tid; i < KH * KW * COUT / 4; i += NTHR_A) // 648 -> <=6 per thread
            cp_async16(dw + i, ws + i);
    };

    int cur = 0;
    load_stage(0, 0);
    cp_commit();

    for (int ic = 0; ic < NICH; ++ic) {
        cp_wait_all();        // buf[cur] data arrived
        __syncthreads();      // visible to all; all warps done with buf[1-cur] compute
        if (ic + 1 < NICH) {  // overlap next load with this compute
            load_stage(1 - cur, ic + 1);
            cp_commit();
        }

        const float* __restrict__ xb = sx[cur];
        const float* __restrict__ wb = sw[cur];
        #pragma unroll 1
        for (int kh = 0; kh < KH; ++kh) {
            const float* xr = &xb[(2 * row + kh) * WIN + cg * 14];
            const float* wr = &wb[(kh * KW) * COUT + ocg * 4];
            #pragma unroll
            for (int kw = 0; kw < KW; ++kw) {
                float4 wv = *reinterpret_cast<const float4*>(wr + kw * COUT);
                float xv[7];
                #pragma unroll
                for (int j = 0; j < 7; ++j) xv[j] = xr[kw + 2 * j];
                #pragma unroll
                for (int j = 0; j < 7; ++j) {
                    acc[j][0] = fmaf(xv[j], wv.x, acc[j][0]);
                    acc[j][1] = fmaf(xv[j], wv.y, acc[j][1]);
                    acc[j][2] = fmaf(xv[j], wv.z, acc[j][2]);
                    acc[j][3] = fmaf(xv[j], wv.w, acc[j][3]);
                }
            }
        }
        cur ^= 1;
    }

    // write partial sums (no bias) to scratch [half][b][oc][oh][ow]
    float* sc = g_scratch + ((size_t)half * B_ + b) * NPOS;
    const int oh = oh0 + row;
    #pragma unroll
    for (int o = 0; o < 4; ++o) {
        const int oc = ocg * 4 + o;
        float* scr = sc + oc * (OH * OW) + oh * OW + cg * 7;
        #pragma unroll
        for (int j = 0; j < 7; ++j) scr[j] = acc[j][o];
    }
}

__global__ __launch_bounds__(256)
void squash_kernel(const float* __restrict__ bias, float* __restrict__ out) {
    int idx = blockIdx.x * 256 + threadIdx.x;
    if (idx >= B_ * NPOS) return;
    int n  = idx % NPOS;
    int oc = n / (OH * OW);
    float v = g_scratch[idx] + g_scratch[B_ * NPOS + idx] + bias[oc];
    float sq = 8.f * v * v;
    float scale = (sq / (1.f + sq)) * rsqrtf(sq + 1e-8f);
    float sv = v * scale;
    float4 f4 = make_float4(sv, sv, sv, sv);
    float4* o4 = reinterpret_cast<float4*>(out);
    o4[(size_t)idx * 2]     = f4;
    o4[(size_t)idx * 2 + 1] = f4;
}

extern "C" void kernel_launch(void* const* d_in, const int* in_sizes, int n_in,
                              void* d_out, int out_size) {
    const float* x    = (const float*)d_in[0];
    const float* W    = (const float*)d_in[1];
    const float* bias = (const float*)d_in[2];
    float* out = (float*)d_out;

    // 1) transpose weights into [ic][k][oc]
    const int wtotal = CIN * KH * KW * COUT;
    transpose_w_kernel<<<(wtotal + 255) / 256, 256>>>(W);

    // 2) conv partial sums, ic split across 2 block sets (448 blocks, fully resident)
    dim3 gridA(OH / THA / 1, 2, B_);          // (7, 2, 32)
    conv_partial_kernel<<<gridA, NTHR_A>>>(x);

    // 3) combine halves + bias + squash + broadcast T=8
    const int total = B_ * NPOS;
    squash_kernel<<<(total + 255) / 256, 256>>>(bias, out);
}